// round 12
// baseline (speedup 1.0000x reference)
#include <cuda_runtime.h>
#include <cuda_fp16.h>
#include <math.h>
#include <stdint.h>

// Problem sizes (fixed)
#define BATCH 2
#define SEQ   4096
#define DIM   1024
#define MTOT  (BATCH * SEQ)     // 8192
#define DE    (2 * DIM)         // 2048  (cos || sin concatenated)
#define KQK   (3 * DIM)         // 3072  (split2 K for QK projection)

// ---------------- scratch (device globals; no allocation allowed) ----------
__device__ __half g_Ax [(size_t)MTOT * KQK];           // [8192][3072] = [xh|xh|xl]
__device__ __half g_Bqk[(size_t)DE * KQK];             // [2048][3072]: Wq/Wk rows [Wh|Wl|Wh]
__device__ __half g_Bv [(size_t)DIM * DIM];            // [1024][1024]: Wv fp16
__device__ float  g_bqk[DE];                           // bq | bk
__device__ float  g_V  [(size_t)MTOT * DIM];           // V fp32
__device__ __half g_Qe [(size_t)MTOT * DE];            // [8192][2048] = [cos|sin]
__device__ __half g_Ke [(size_t)MTOT * DE];
__device__ __half g_Vt [(size_t)MTOT * DIM];           // per batch [DIM][SEQ]
__device__ float  g_S  [(size_t)BATCH * SEQ * SEQ];    // scores fp32 (134 MB)
__device__ __half g_P  [(size_t)BATCH * SEQ * SEQ];    // weights fp16 (67 MB)

// ============================ helpers =======================================
__device__ __forceinline__ uint32_t smem_u32(const void* p) {
    uint32_t a;
    asm("{ .reg .u64 t; cvta.to.shared.u64 t, %1; cvt.u32.u64 %0, t; }"
        : "=r"(a) : "l"(p));
    return a;
}

__device__ __forceinline__ void cpasync16(uint32_t saddr, const void* gaddr) {
    asm volatile("cp.async.cg.shared.global [%0], [%1], 16;"
                 :: "r"(saddr), "l"(gaddr) : "memory");
}

__device__ __forceinline__ void ldsm_x4(uint32_t r[4], uint32_t addr) {
    asm volatile("ldmatrix.sync.aligned.m8n8.x4.shared.b16 {%0,%1,%2,%3}, [%4];"
                 : "=r"(r[0]), "=r"(r[1]), "=r"(r[2]), "=r"(r[3])
                 : "r"(addr));
}

__device__ __forceinline__ void mma_f16(float c[4], const uint32_t a[4],
                                        const uint32_t b[2]) {
    asm volatile(
        "mma.sync.aligned.m16n8k16.row.col.f32.f16.f16.f32 "
        "{%0,%1,%2,%3}, {%4,%5,%6,%7}, {%8,%9}, {%0,%1,%2,%3};"
        : "+f"(c[0]), "+f"(c[1]), "+f"(c[2]), "+f"(c[3])
        : "r"(a[0]), "r"(a[1]), "r"(a[2]), "r"(a[3]),
          "r"(b[0]), "r"(b[1]));
}

#define EPI_STORE 0   // fp32 C (+bias)
#define EPI_THETA 1   // QK projection: sincos(Q*inv_wl + pb) -> Qe/Ke fp16

// ============================================================================
// fp16 tensor-core NT GEMM via mma.sync.m16n8k16:
//   acc[M,N] = A[M,K] @ B[N,K]^T, fp32 accumulate.
// CTA tile 128(M) x 256(N), k-tile = 64 halfs, 3-stage cp.async ring,
// 256 threads (8 warps, 2x4 grid, WARP TILE 64x64 -> 128 acc regs: 2x the
// MMA work per fragment byte vs 64x32; MMA:crossbar = 2:1). 1 CTA/SM
// (162 KB smem, ~220 regs), 144B-padded rows (conflict-free ldmatrix),
// fragment double-buffering, one barrier per k-tile.
// EPI_STORE: C fp32 (+bias).  EPI_THETA: fused Euler phase epilogue.
// M%128==0, N%256==0, K%64==0.
// ============================================================================
#define H_STAGE_BYTES  55296              // (128 + 256) rows * 144 B
#define H_ABYTES       18432              // 128 rows * 144
#define H_SMEM_BYTES   (3 * H_STAGE_BYTES)

template<int EPI>
__global__ void __launch_bounds__(256, 1)
hgemm_nt(const __half* __restrict__ A, const __half* __restrict__ B,
         const float* __restrict__ bias, float* __restrict__ C,
         __half* __restrict__ Qe, __half* __restrict__ Ke,
         const float* __restrict__ pb,
         int Nld, int K, int lda, int ldb,
         size_t strA, size_t strB, size_t strC)
{
    extern __shared__ float dynsmem[];
    const uint32_t sb = smem_u32(dynsmem);

    const int tid  = threadIdx.x;
    const int wid  = tid >> 5;
    const int lane = tid & 31;

    A += strA * blockIdx.z;
    B += strB * blockIdx.z;
    C += strC * blockIdx.z;
    const int tileM = blockIdx.y * 128;
    const int tileN = blockIdx.x * 256;

    // ---- loader: A rows baseRow+32i (i<4); B rows baseRow+32i (i<8)
    const int baseRow = tid >> 3;      // 0..31
    const int seg     = tid & 7;       // 0..7
    const __half* Ath = A + (size_t)(tileM + baseRow) * lda + seg * 8;
    const __half* Bth = B + (size_t)(tileN + baseRow) * ldb + seg * 8;
    const uint32_t thoff = (uint32_t)(baseRow * 144 + seg * 16);

#define ISSUE_STAGE(KT, S) do {                                               \
    uint32_t _sa = sb + (uint32_t)(S) * H_STAGE_BYTES + thoff;                \
    const __half* _ga = Ath + (size_t)(KT) * 64;                              \
    const __half* _gb = Bth + (size_t)(KT) * 64;                              \
    _Pragma("unroll")                                                         \
    for (int _i = 0; _i < 4; _i++)                                            \
        cpasync16(_sa + _i * (32u * 144u), _ga + (size_t)_i * 32 * lda);      \
    _Pragma("unroll")                                                         \
    for (int _i = 0; _i < 8; _i++)                                            \
        cpasync16(_sa + H_ABYTES + _i * (32u * 144u), _gb + (size_t)_i * 32 * ldb); \
    asm volatile("cp.async.commit_group;" ::: "memory");                      \
} while (0)

    const int nkt = K >> 6;            // 64 halfs per k-tile
    ISSUE_STAGE(0, 0);
    ISSUE_STAGE(1, 1);

    // ---- compute mapping: 2x4 warp grid, warp tile 64x64
    const int warp_m = wid >> 2;       // 0..1  -> 64 rows
    const int warp_n = wid & 3;        // 0..3  -> 64 cols
    const int g   = lane >> 2;         // 0..7
    const int tig = lane & 3;          // 0..3

    const uint32_t laneA = (uint32_t)((lane & 15) * 144 + (lane >> 4) * 16);
    const uint32_t laneB = (uint32_t)(((lane & 7) + ((lane >> 4) & 1) * 8) * 144
                                      + ((lane >> 3) & 1) * 16);

#define LOAD_FRAGS(BUF, KS) do {                                              \
    _Pragma("unroll")                                                         \
    for (int _mi = 0; _mi < 4; _mi++)                                         \
        ldsm_x4(afr[BUF][_mi], aBase + _mi * 2304u + (KS) * 32u);             \
    _Pragma("unroll")                                                         \
    for (int _nb = 0; _nb < 4; _nb++) {                                       \
        uint32_t _t[4];                                                       \
        ldsm_x4(_t, bBase + _nb * 2304u + (KS) * 32u);                        \
        bfr[BUF][2 * _nb + 0][0] = _t[0]; bfr[BUF][2 * _nb + 0][1] = _t[1];   \
        bfr[BUF][2 * _nb + 1][0] = _t[2]; bfr[BUF][2 * _nb + 1][1] = _t[3];   \
    }                                                                         \
} while (0)

    float acc[4][8][4];
#pragma unroll
    for (int mi = 0; mi < 4; mi++)
#pragma unroll
        for (int nj = 0; nj < 8; nj++)
#pragma unroll
            for (int r = 0; r < 4; r++) acc[mi][nj][r] = 0.0f;

    int s = 0;   // stage of tile kt
    for (int kt = 0; kt < nkt; ++kt) {
        if (kt + 2 < nkt) {
            asm volatile("cp.async.wait_group 1;" ::: "memory");
        } else {
            asm volatile("cp.async.wait_group 0;" ::: "memory");
        }
        __syncthreads();   // tile kt visible + all warps done with kt-1's stage

        if (kt + 2 < nkt) {
            const int s2 = (s + 2 >= 3) ? (s - 1) : (s + 2);
            ISSUE_STAGE(kt + 2, s2);
        }

        const uint32_t stAddr = sb + (uint32_t)s * H_STAGE_BYTES;
        const uint32_t aBase = stAddr + (uint32_t)(warp_m * 64) * 144 + laneA;
        const uint32_t bBase = stAddr + H_ABYTES + (uint32_t)(warp_n * 64) * 144 + laneB;

        uint32_t afr[2][4][4];
        uint32_t bfr[2][8][2];
        LOAD_FRAGS(0, 0);

#pragma unroll
        for (int ks = 0; ks < 4; ++ks) {
            const int cur = ks & 1;
            if (ks < 3) LOAD_FRAGS(cur ^ 1, ks + 1);
#pragma unroll
            for (int mi = 0; mi < 4; mi++)
#pragma unroll
                for (int nj = 0; nj < 8; nj++)
                    mma_f16(acc[mi][nj], afr[cur][mi], bfr[cur][nj]);
        }
        s = (s + 1 == 3) ? 0 : (s + 1);
    }
#undef ISSUE_STAGE
#undef LOAD_FRAGS

    if (EPI == EPI_STORE) {
#pragma unroll
        for (int mi = 0; mi < 4; mi++) {
            const int row0 = tileM + warp_m * 64 + mi * 16 + g;
#pragma unroll
            for (int nj = 0; nj < 8; nj++) {
                const int col = tileN + warp_n * 64 + nj * 8 + 2 * tig;
                float2 bv = {0.0f, 0.0f};
                if (bias) bv = *(const float2*)(bias + col);
                float2 lo = { acc[mi][nj][0] + bv.x, acc[mi][nj][1] + bv.y };
                float2 hi = { acc[mi][nj][2] + bv.x, acc[mi][nj][3] + bv.y };
                *(float2*)(C + (size_t)row0 * Nld + col)       = lo;
                *(float2*)(C + (size_t)(row0 + 8) * Nld + col) = hi;
            }
        }
    } else {
        // EPI_THETA: acc = Q or K pre-bias, fp32-exact. col in [0,2048):
        // col < 1024 -> Q col d; col >= 1024 -> K col d-1024.
        const float WLC = (float)(6.283185307179586 / (double)DIM);
#pragma unroll
        for (int mi = 0; mi < 4; mi++) {
            const int row0 = tileM + warp_m * 64 + mi * 16 + g;
#pragma unroll
            for (int nj = 0; nj < 8; nj++) {
                const int col = tileN + warp_n * 64 + nj * 8 + 2 * tig;
                const int d   = col & (DIM - 1);
                __half* dst = (col < DIM) ? Qe : Ke;
                float2 bv = *(const float2*)(bias + col);
                float inv0 = 1.0f / ((float)(d + 1) * WLC + 1e-8f);
                float inv1 = 1.0f / ((float)(d + 2) * WLC + 1e-8f);
                float p0 = pb[d], p1 = pb[d + 1];
#pragma unroll
                for (int h = 0; h < 2; h++) {       // rows row0, row0+8
                    const int row = row0 + 8 * h;
                    float q0 = acc[mi][nj][2 * h + 0] + bv.x;
                    float q1 = acc[mi][nj][2 * h + 1] + bv.y;
                    float s0, c0, s1, c1;
                    sincosf(fmaf(q0, inv0, p0), &s0, &c0);
                    sincosf(fmaf(q1, inv1, p1), &s1, &c1);
                    __half* base = dst + (size_t)row * DE + d;
                    *(__half2*)(base)       = __floats2half2_rn(c0, c1);
                    *(__half2*)(base + DIM) = __floats2half2_rn(s0, s1);
                }
            }
        }
    }
}

// ---------------------------------------------------------------------------
// prep: fp16 split2 operands.
// A' = [xh | xh | xl]; Bqk rows (Wq then Wk): [Wh | Wl | Wh]; Bv = Wv fp16.
// ---------------------------------------------------------------------------
__global__ void __launch_bounds__(256)
convert_x(const float* __restrict__ x, __half* __restrict__ Ax)
{
    const int idx = blockIdx.x * blockDim.x + threadIdx.x;   // < MTOT*DIM
    const int m = idx >> 10;
    const int d = idx & (DIM - 1);
    float v = x[idx];
    __half h = __float2half_rn(v);
    __half l = __float2half_rn(v - __half2float(h));
    size_t base = (size_t)m * KQK;
    Ax[base + d]            = h;
    Ax[base + DIM + d]      = h;
    Ax[base + 2 * DIM + d]  = l;
}

__global__ void __launch_bounds__(256)
convert_w(const float* __restrict__ Wq, const float* __restrict__ Wk,
          const float* __restrict__ Wv,
          __half* __restrict__ Bqk, __half* __restrict__ Bv)
{
    const int idx = blockIdx.x * blockDim.x + threadIdx.x;   // < DIM*DIM
    const int n = idx >> 10;
    const int k = idx & (DIM - 1);
    {
        float v = Wq[idx];
        __half h = __float2half_rn(v);
        __half l = __float2half_rn(v - __half2float(h));
        size_t base = (size_t)n * KQK;
        Bqk[base + k]           = h;
        Bqk[base + DIM + k]     = l;
        Bqk[base + 2 * DIM + k] = h;
    }
    {
        float v = Wk[idx];
        __half h = __float2half_rn(v);
        __half l = __float2half_rn(v - __half2float(h));
        size_t base = (size_t)(DIM + n) * KQK;
        Bqk[base + k]           = h;
        Bqk[base + DIM + k]     = l;
        Bqk[base + 2 * DIM + k] = h;
    }
    Bv[idx] = __float2half_rn(Wv[idx]);
}

__global__ void __launch_bounds__(256)
concat_bias(const float* __restrict__ bq, const float* __restrict__ bk,
            float* __restrict__ b2)
{
    const int i = blockIdx.x * blockDim.x + threadIdx.x;     // < DE
    b2[i] = (i < DIM) ? bq[i] : bk[i - DIM];
}

// ---------------------------------------------------------------------------
// V transpose per batch -> fp16: Vt[b][n][s] = fp16(V[b*4096+s][n])
// ---------------------------------------------------------------------------
__global__ void __launch_bounds__(256)
transpose_v(const float* __restrict__ V, __half* __restrict__ Vt)
{
    __shared__ float t[32][33];
    const int b  = blockIdx.z;
    const int s0 = blockIdx.y * 32;
    const int n0 = blockIdx.x * 32;
    const int x = threadIdx.x, y = threadIdx.y;   // 32 x 8
#pragma unroll
    for (int i = 0; i < 32; i += 8)
        t[y + i][x] = V[(size_t)(b * SEQ + s0 + y + i) * DIM + n0 + x];
    __syncthreads();
    __half* Vb = Vt + (size_t)b * DIM * SEQ;
#pragma unroll
    for (int i = 0; i < 32; i += 8)
        Vb[(size_t)(n0 + y + i) * SEQ + s0 + x] = __float2half_rn(t[x][y + i]);
}

// ---------------------------------------------------------------------------
// softmax rows (len SEQ), logits /32; writes fp16 weights to P.
// ---------------------------------------------------------------------------
__global__ void __launch_bounds__(256)
softmax_rows(const float* __restrict__ S, __half* __restrict__ P)
{
    __shared__ float sm[8];
    const float* p = S + (size_t)blockIdx.x * SEQ;
    __half* po = P + (size_t)blockIdx.x * SEQ;
    const float4* p4 = (const float4*)p;
    const int t    = threadIdx.x;
    const int lane = t & 31;
    const int wid  = t >> 5;
    const float SCALE = 0.03125f;   // 1/sqrt(1024)

    float v[16];
    float mx = -1e30f;
#pragma unroll
    for (int i = 0; i < 4; i++) {
        float4 x = p4[t + i * 256];
        v[4*i+0] = x.x * SCALE; v[4*i+1] = x.y * SCALE;
        v[4*i+2] = x.z * SCALE; v[4*i+3] = x.w * SCALE;
        mx = fmaxf(mx, fmaxf(fmaxf(v[4*i+0], v[4*i+1]),
                             fmaxf(v[4*i+2], v[4*i+3])));
    }
#pragma unroll
    for (int off = 16; off >= 1; off >>= 1)
        mx = fmaxf(mx, __shfl_xor_sync(0xffffffffu, mx, off));
    if (lane == 0) sm[wid] = mx;
    __syncthreads();
    mx = sm[0];
#pragma unroll
    for (int w = 1; w < 8; w++) mx = fmaxf(mx, sm[w]);
    __syncthreads();

    float sum = 0.0f;
#pragma unroll
    for (int i = 0; i < 16; i++) { v[i] = expf(v[i] - mx); sum += v[i]; }
#pragma unroll
    for (int off = 16; off >= 1; off >>= 1)
        sum += __shfl_xor_sync(0xffffffffu, sum, off);
    if (lane == 0) sm[wid] = sum;
    __syncthreads();
    sum = sm[0];
#pragma unroll
    for (int w = 1; w < 8; w++) sum += sm[w];
    float inv = 1.0f / sum;

    __half2* po2 = (__half2*)po;
#pragma unroll
    for (int i = 0; i < 4; i++) {
        const int e = 4 * (t + i * 256);
        po2[e / 2]     = __floats2half2_rn(v[4*i+0] * inv, v[4*i+1] * inv);
        po2[e / 2 + 1] = __floats2half2_rn(v[4*i+2] * inv, v[4*i+3] * inv);
    }
}

// ---------------------------------------------------------------------------
extern "C" void kernel_launch(void* const* d_in, const int* in_sizes, int n_in,
                              void* d_out, int out_size)
{
    const float* x  = (const float*)d_in[0];
    const float* Wq = (const float*)d_in[1];
    const float* bq = (const float*)d_in[2];
    const float* Wk = (const float*)d_in[3];
    const float* bk = (const float*)d_in[4];
    const float* Wv = (const float*)d_in[5];
    const float* bv = (const float*)d_in[6];
    const float* pb = (const float*)d_in[7];
    float* out = (float*)d_out;

    __half *Ax, *Bqk, *Bv, *Qe, *Ke, *Vt, *P;
    float *b2, *V, *Sm;
    cudaGetSymbolAddress((void**)&Ax,  g_Ax);
    cudaGetSymbolAddress((void**)&Bqk, g_Bqk);
    cudaGetSymbolAddress((void**)&Bv,  g_Bv);
    cudaGetSymbolAddress((void**)&b2,  g_bqk);
    cudaGetSymbolAddress((void**)&V,   g_V);
    cudaGetSymbolAddress((void**)&Qe,  g_Qe);
    cudaGetSymbolAddress((void**)&Ke,  g_Ke);
    cudaGetSymbolAddress((void**)&Vt,  g_Vt);
    cudaGetSymbolAddress((void**)&Sm,  g_S);
    cudaGetSymbolAddress((void**)&P,   g_P);

    cudaFuncSetAttribute(hgemm_nt<EPI_STORE>,
                         cudaFuncAttributeMaxDynamicSharedMemorySize,
                         H_SMEM_BYTES);
    cudaFuncSetAttribute(hgemm_nt<EPI_THETA>,
                         cudaFuncAttributeMaxDynamicSharedMemorySize,
                         H_SMEM_BYTES);

    // 0) build fp16 operands
    convert_x<<<(MTOT * DIM) / 256, 256>>>(x, Ax);
    convert_w<<<(DIM * DIM) / 256, 256>>>(Wq, Wk, Wv, Bqk, Bv);
    concat_bias<<<DE / 256, 256>>>(bq, bk, b2);

    // 1) QK projection (split2, K=3072) with fused theta epilogue -> Qe, Ke
    dim3 gQK(DE / 256, MTOT / 128, 1);
    hgemm_nt<EPI_THETA><<<gQK, 256, H_SMEM_BYTES>>>(
        Ax, Bqk, b2, nullptr, Qe, Ke, pb,
        DE, KQK, KQK, KQK, 0, 0, 0);

    // 2) V projection (plain fp16, K=1024) -> V fp32
    dim3 gV(DIM / 256, MTOT / 128, 1);
    hgemm_nt<EPI_STORE><<<gV, 256, H_SMEM_BYTES>>>(
        Ax, Bv, bv, V, nullptr, nullptr, nullptr,
        DIM, DIM, KQK, DIM, 0, 0, 0);

    // 3) V transpose -> fp16 [DIM][SEQ] per batch
    dim3 gT(DIM / 32, SEQ / 32, BATCH);
    transpose_v<<<gT, dim3(32, 8)>>>(V, Vt);

    // 4) sim = Qe @ Ke^T per batch (fp16 mma k16)
    dim3 gSim(SEQ / 256, SEQ / 128, BATCH);
    hgemm_nt<EPI_STORE><<<gSim, 256, H_SMEM_BYTES>>>(
        Qe, Ke, nullptr, Sm, nullptr, nullptr, nullptr,
        SEQ, DE, DE, DE,
        (size_t)SEQ * DE, (size_t)SEQ * DE, (size_t)SEQ * SEQ);

    // 5) softmax(sim / 32) rows -> fp16 weights
    softmax_rows<<<BATCH * SEQ, 256>>>(Sm, P);

    // 6) out = P @ Vt^T per batch (fp16 mma k16)
    dim3 gPV(DIM / 256, SEQ / 128, BATCH);
    hgemm_nt<EPI_STORE><<<gPV, 256, H_SMEM_BYTES>>>(
        P, Vt, nullptr, out, nullptr, nullptr, nullptr,
        DIM, SEQ, SEQ, SEQ,
        (size_t)SEQ * SEQ, (size_t)DIM * SEQ, (size_t)SEQ * DIM);
}

// round 13
// speedup vs baseline: 1.0803x; 1.0803x over previous
#include <cuda_runtime.h>
#include <cuda_fp16.h>
#include <math.h>
#include <stdint.h>

// Problem sizes (fixed)
#define BATCH 2
#define SEQ   4096
#define DIM   1024
#define MTOT  (BATCH * SEQ)     // 8192
#define DE    (2 * DIM)         // 2048  (cos || sin concatenated)
#define KQK   (3 * DIM)         // 3072  (split2 K for QK projection)

// ---------------- scratch (device globals; no allocation allowed) ----------
__device__ __half g_Ax [(size_t)MTOT * KQK];           // [8192][3072] = [xh|xh|xl]
__device__ __half g_Bqk[(size_t)DE * KQK];             // [2048][3072]: Wq/Wk rows [Wh|Wl|Wh]
__device__ __half g_Bv [(size_t)DIM * DIM];            // [1024][1024]: Wv fp16
__device__ float  g_bqk[DE];                           // bq | bk
__device__ float  g_V  [(size_t)MTOT * DIM];           // V fp32
__device__ __half g_Qe [(size_t)MTOT * DE];            // [8192][2048] = [cos|sin]
__device__ __half g_Ke [(size_t)MTOT * DE];
__device__ __half g_Vt [(size_t)MTOT * DIM];           // per batch [DIM][SEQ]
__device__ float  g_S  [(size_t)BATCH * SEQ * SEQ];    // scores fp32 (134 MB)
__device__ __half g_P  [(size_t)BATCH * SEQ * SEQ];    // weights fp16 (67 MB)

// ============================ helpers =======================================
__device__ __forceinline__ uint32_t smem_u32(const void* p) {
    uint32_t a;
    asm("{ .reg .u64 t; cvta.to.shared.u64 t, %1; cvt.u32.u64 %0, t; }"
        : "=r"(a) : "l"(p));
    return a;
}

__device__ __forceinline__ void cpasync16(uint32_t saddr, const void* gaddr) {
    asm volatile("cp.async.cg.shared.global [%0], [%1], 16;"
                 :: "r"(saddr), "l"(gaddr) : "memory");
}

__device__ __forceinline__ void ldsm_x4(uint32_t r[4], uint32_t addr) {
    asm volatile("ldmatrix.sync.aligned.m8n8.x4.shared.b16 {%0,%1,%2,%3}, [%4];"
                 : "=r"(r[0]), "=r"(r[1]), "=r"(r[2]), "=r"(r[3])
                 : "r"(addr));
}

__device__ __forceinline__ void mma_f16(float c[4], const uint32_t a[4],
                                        const uint32_t b[2]) {
    asm volatile(
        "mma.sync.aligned.m16n8k16.row.col.f32.f16.f16.f32 "
        "{%0,%1,%2,%3}, {%4,%5,%6,%7}, {%8,%9}, {%0,%1,%2,%3};"
        : "+f"(c[0]), "+f"(c[1]), "+f"(c[2]), "+f"(c[3])
        : "r"(a[0]), "r"(a[1]), "r"(a[2]), "r"(a[3]),
          "r"(b[0]), "r"(b[1]));
}

#define EPI_STORE 0   // fp32 C (+bias)
#define EPI_THETA 1   // QK projection: sincos(Q*inv_wl + pb) -> Qe/Ke fp16

// ============================================================================
// fp16 tensor-core NT GEMM via mma.sync.m16n8k16:
//   acc[M,N] = A[M,K] @ B[N,K]^T, fp32 accumulate.
// CTA tile 128x128, k-tile 64 halfs, 3-stage cp.async ring (110 KB smem ->
// 2 CTAs/SM), 128 THREADS = 4 warps (2x2 grid, WARP TILE 64x64 -> 128 acc
// regs, A-frags reused 8x). __launch_bounds__(128,2) -> 255-reg cap, 2 CTAs
// co-resident. 144B-padded rows (conflict-free ldmatrix), fragment
// double-buffering, one barrier per k-tile.
// M%128==0, N%128==0, K%64==0.
// ============================================================================
#define H_STAGE_BYTES  36864              // 2 * 128 rows * 144 B
#define H_ABYTES       18432              // 128 rows * 144
#define H_SMEM_BYTES   (3 * H_STAGE_BYTES)

template<int EPI>
__global__ void __launch_bounds__(128, 2)
hgemm_nt(const __half* __restrict__ A, const __half* __restrict__ B,
         const float* __restrict__ bias, float* __restrict__ C,
         __half* __restrict__ Qe, __half* __restrict__ Ke,
         const float* __restrict__ pb,
         int Nld, int K, int lda, int ldb,
         size_t strA, size_t strB, size_t strC)
{
    extern __shared__ float dynsmem[];
    const uint32_t sb = smem_u32(dynsmem);

    const int tid  = threadIdx.x;
    const int wid  = tid >> 5;         // 0..3
    const int lane = tid & 31;

    A += strA * blockIdx.z;
    B += strB * blockIdx.z;
    C += strC * blockIdx.z;
    const int tileM = blockIdx.y * 128;
    const int tileN = blockIdx.x * 128;

    // ---- loader: thread covers rows baseRow + 16*i (i<8), 16B seg of 128B row
    const int baseRow = tid >> 3;      // 0..15
    const int seg     = tid & 7;       // 0..7
    const __half* Ath = A + (size_t)(tileM + baseRow) * lda + seg * 8;
    const __half* Bth = B + (size_t)(tileN + baseRow) * ldb + seg * 8;
    const uint32_t thoff = (uint32_t)(baseRow * 144 + seg * 16);

#define ISSUE_STAGE(KT, S) do {                                               \
    uint32_t _sa = sb + (uint32_t)(S) * H_STAGE_BYTES + thoff;                \
    const __half* _ga = Ath + (size_t)(KT) * 64;                              \
    const __half* _gb = Bth + (size_t)(KT) * 64;                              \
    _Pragma("unroll")                                                         \
    for (int _i = 0; _i < 8; _i++)                                            \
        cpasync16(_sa + _i * 2304u, _ga + (size_t)_i * 16 * lda);             \
    _Pragma("unroll")                                                         \
    for (int _i = 0; _i < 8; _i++)                                            \
        cpasync16(_sa + H_ABYTES + _i * 2304u, _gb + (size_t)_i * 16 * ldb);  \
    asm volatile("cp.async.commit_group;" ::: "memory");                      \
} while (0)

    const int nkt = K >> 6;            // 64 halfs per k-tile
    ISSUE_STAGE(0, 0);
    ISSUE_STAGE(1, 1);

    // ---- compute mapping: 2x2 warp grid, warp tile 64x64
    const int warp_m = wid >> 1;       // 0..1 -> 64 rows
    const int warp_n = wid & 1;        // 0..1 -> 64 cols
    const int g   = lane >> 2;         // 0..7
    const int tig = lane & 3;          // 0..3

    const uint32_t laneA = (uint32_t)((lane & 15) * 144 + (lane >> 4) * 16);
    const uint32_t laneB = (uint32_t)(((lane & 7) + ((lane >> 4) & 1) * 8) * 144
                                      + ((lane >> 3) & 1) * 16);

#define LOAD_FRAGS(BUF, KS) do {                                              \
    _Pragma("unroll")                                                         \
    for (int _mi = 0; _mi < 4; _mi++)                                         \
        ldsm_x4(afr[BUF][_mi], aBase + _mi * 2304u + (KS) * 32u);             \
    _Pragma("unroll")                                                         \
    for (int _nb = 0; _nb < 4; _nb++) {                                       \
        uint32_t _t[4];                                                       \
        ldsm_x4(_t, bBase + _nb * 2304u + (KS) * 32u);                        \
        bfr[BUF][2 * _nb + 0][0] = _t[0]; bfr[BUF][2 * _nb + 0][1] = _t[1];   \
        bfr[BUF][2 * _nb + 1][0] = _t[2]; bfr[BUF][2 * _nb + 1][1] = _t[3];   \
    }                                                                         \
} while (0)

    float acc[4][8][4];
#pragma unroll
    for (int mi = 0; mi < 4; mi++)
#pragma unroll
        for (int nj = 0; nj < 8; nj++)
#pragma unroll
            for (int r = 0; r < 4; r++) acc[mi][nj][r] = 0.0f;

    int s = 0;   // stage of tile kt
    for (int kt = 0; kt < nkt; ++kt) {
        if (kt + 2 < nkt) {
            asm volatile("cp.async.wait_group 1;" ::: "memory");
        } else {
            asm volatile("cp.async.wait_group 0;" ::: "memory");
        }
        __syncthreads();   // tile kt visible + all warps done with kt-1's stage

        if (kt + 2 < nkt) {
            const int s2 = (s + 2 >= 3) ? (s - 1) : (s + 2);
            ISSUE_STAGE(kt + 2, s2);
        }

        const uint32_t stAddr = sb + (uint32_t)s * H_STAGE_BYTES;
        const uint32_t aBase = stAddr + (uint32_t)(warp_m * 64) * 144 + laneA;
        const uint32_t bBase = stAddr + H_ABYTES + (uint32_t)(warp_n * 64) * 144 + laneB;

        uint32_t afr[2][4][4];
        uint32_t bfr[2][8][2];
        LOAD_FRAGS(0, 0);

#pragma unroll
        for (int ks = 0; ks < 4; ++ks) {
            const int cur = ks & 1;
            if (ks < 3) LOAD_FRAGS(cur ^ 1, ks + 1);
#pragma unroll
            for (int mi = 0; mi < 4; mi++)
#pragma unroll
                for (int nj = 0; nj < 8; nj++)
                    mma_f16(acc[mi][nj], afr[cur][mi], bfr[cur][nj]);
        }
        s = (s + 1 == 3) ? 0 : (s + 1);
    }
#undef ISSUE_STAGE
#undef LOAD_FRAGS

    if (EPI == EPI_STORE) {
#pragma unroll
        for (int mi = 0; mi < 4; mi++) {
            const int row0 = tileM + warp_m * 64 + mi * 16 + g;
#pragma unroll
            for (int nj = 0; nj < 8; nj++) {
                const int col = tileN + warp_n * 64 + nj * 8 + 2 * tig;
                float2 bv = {0.0f, 0.0f};
                if (bias) bv = *(const float2*)(bias + col);
                float2 lo = { acc[mi][nj][0] + bv.x, acc[mi][nj][1] + bv.y };
                float2 hi = { acc[mi][nj][2] + bv.x, acc[mi][nj][3] + bv.y };
                *(float2*)(C + (size_t)row0 * Nld + col)       = lo;
                *(float2*)(C + (size_t)(row0 + 8) * Nld + col) = hi;
            }
        }
    } else {
        // EPI_THETA: acc = Q or K pre-bias, fp32-exact. col in [0,2048):
        // col < 1024 -> Q col d; col >= 1024 -> K col d-1024.
        const float WLC = (float)(6.283185307179586 / (double)DIM);
#pragma unroll
        for (int mi = 0; mi < 4; mi++) {
            const int row0 = tileM + warp_m * 64 + mi * 16 + g;
#pragma unroll
            for (int nj = 0; nj < 8; nj++) {
                const int col = tileN + warp_n * 64 + nj * 8 + 2 * tig;
                const int d   = col & (DIM - 1);
                __half* dst = (col < DIM) ? Qe : Ke;
                float2 bv = *(const float2*)(bias + col);
                float inv0 = 1.0f / ((float)(d + 1) * WLC + 1e-8f);
                float inv1 = 1.0f / ((float)(d + 2) * WLC + 1e-8f);
                float p0 = pb[d], p1 = pb[d + 1];
#pragma unroll
                for (int h = 0; h < 2; h++) {       // rows row0, row0+8
                    const int row = row0 + 8 * h;
                    float q0 = acc[mi][nj][2 * h + 0] + bv.x;
                    float q1 = acc[mi][nj][2 * h + 1] + bv.y;
                    float s0, c0, s1, c1;
                    sincosf(fmaf(q0, inv0, p0), &s0, &c0);
                    sincosf(fmaf(q1, inv1, p1), &s1, &c1);
                    __half* base = dst + (size_t)row * DE + d;
                    *(__half2*)(base)       = __floats2half2_rn(c0, c1);
                    *(__half2*)(base + DIM) = __floats2half2_rn(s0, s1);
                }
            }
        }
    }
}

// ---------------------------------------------------------------------------
// prep: fp16 split2 operands.
// A' = [xh | xh | xl]; Bqk rows (Wq then Wk): [Wh | Wl | Wh]; Bv = Wv fp16.
// ---------------------------------------------------------------------------
__global__ void __launch_bounds__(256)
convert_x(const float* __restrict__ x, __half* __restrict__ Ax)
{
    const int idx = blockIdx.x * blockDim.x + threadIdx.x;   // < MTOT*DIM
    const int m = idx >> 10;
    const int d = idx & (DIM - 1);
    float v = x[idx];
    __half h = __float2half_rn(v);
    __half l = __float2half_rn(v - __half2float(h));
    size_t base = (size_t)m * KQK;
    Ax[base + d]            = h;
    Ax[base + DIM + d]      = h;
    Ax[base + 2 * DIM + d]  = l;
}

__global__ void __launch_bounds__(256)
convert_w(const float* __restrict__ Wq, const float* __restrict__ Wk,
          const float* __restrict__ Wv,
          __half* __restrict__ Bqk, __half* __restrict__ Bv)
{
    const int idx = blockIdx.x * blockDim.x + threadIdx.x;   // < DIM*DIM
    const int n = idx >> 10;
    const int k = idx & (DIM - 1);
    {
        float v = Wq[idx];
        __half h = __float2half_rn(v);
        __half l = __float2half_rn(v - __half2float(h));
        size_t base = (size_t)n * KQK;
        Bqk[base + k]           = h;
        Bqk[base + DIM + k]     = l;
        Bqk[base + 2 * DIM + k] = h;
    }
    {
        float v = Wk[idx];
        __half h = __float2half_rn(v);
        __half l = __float2half_rn(v - __half2float(h));
        size_t base = (size_t)(DIM + n) * KQK;
        Bqk[base + k]           = h;
        Bqk[base + DIM + k]     = l;
        Bqk[base + 2 * DIM + k] = h;
    }
    Bv[idx] = __float2half_rn(Wv[idx]);
}

__global__ void __launch_bounds__(256)
concat_bias(const float* __restrict__ bq, const float* __restrict__ bk,
            float* __restrict__ b2)
{
    const int i = blockIdx.x * blockDim.x + threadIdx.x;     // < DE
    b2[i] = (i < DIM) ? bq[i] : bk[i - DIM];
}

// ---------------------------------------------------------------------------
// V transpose per batch -> fp16: Vt[b][n][s] = fp16(V[b*4096+s][n])
// ---------------------------------------------------------------------------
__global__ void __launch_bounds__(256)
transpose_v(const float* __restrict__ V, __half* __restrict__ Vt)
{
    __shared__ float t[32][33];
    const int b  = blockIdx.z;
    const int s0 = blockIdx.y * 32;
    const int n0 = blockIdx.x * 32;
    const int x = threadIdx.x, y = threadIdx.y;   // 32 x 8
#pragma unroll
    for (int i = 0; i < 32; i += 8)
        t[y + i][x] = V[(size_t)(b * SEQ + s0 + y + i) * DIM + n0 + x];
    __syncthreads();
    __half* Vb = Vt + (size_t)b * DIM * SEQ;
#pragma unroll
    for (int i = 0; i < 32; i += 8)
        Vb[(size_t)(n0 + y + i) * SEQ + s0 + x] = __float2half_rn(t[x][y + i]);
}

// ---------------------------------------------------------------------------
// softmax rows (len SEQ), logits /32; writes fp16 weights to P.
// ---------------------------------------------------------------------------
__global__ void __launch_bounds__(256)
softmax_rows(const float* __restrict__ S, __half* __restrict__ P)
{
    __shared__ float sm[8];
    const float* p = S + (size_t)blockIdx.x * SEQ;
    __half* po = P + (size_t)blockIdx.x * SEQ;
    const float4* p4 = (const float4*)p;
    const int t    = threadIdx.x;
    const int lane = t & 31;
    const int wid  = t >> 5;
    const float SCALE = 0.03125f;   // 1/sqrt(1024)

    float v[16];
    float mx = -1e30f;
#pragma unroll
    for (int i = 0; i < 4; i++) {
        float4 x = p4[t + i * 256];
        v[4*i+0] = x.x * SCALE; v[4*i+1] = x.y * SCALE;
        v[4*i+2] = x.z * SCALE; v[4*i+3] = x.w * SCALE;
        mx = fmaxf(mx, fmaxf(fmaxf(v[4*i+0], v[4*i+1]),
                             fmaxf(v[4*i+2], v[4*i+3])));
    }
#pragma unroll
    for (int off = 16; off >= 1; off >>= 1)
        mx = fmaxf(mx, __shfl_xor_sync(0xffffffffu, mx, off));
    if (lane == 0) sm[wid] = mx;
    __syncthreads();
    mx = sm[0];
#pragma unroll
    for (int w = 1; w < 8; w++) mx = fmaxf(mx, sm[w]);
    __syncthreads();

    float sum = 0.0f;
#pragma unroll
    for (int i = 0; i < 16; i++) { v[i] = expf(v[i] - mx); sum += v[i]; }
#pragma unroll
    for (int off = 16; off >= 1; off >>= 1)
        sum += __shfl_xor_sync(0xffffffffu, sum, off);
    if (lane == 0) sm[wid] = sum;
    __syncthreads();
    sum = sm[0];
#pragma unroll
    for (int w = 1; w < 8; w++) sum += sm[w];
    float inv = 1.0f / sum;

    __half2* po2 = (__half2*)po;
#pragma unroll
    for (int i = 0; i < 4; i++) {
        const int e = 4 * (t + i * 256);
        po2[e / 2]     = __floats2half2_rn(v[4*i+0] * inv, v[4*i+1] * inv);
        po2[e / 2 + 1] = __floats2half2_rn(v[4*i+2] * inv, v[4*i+3] * inv);
    }
}

// ---------------------------------------------------------------------------
extern "C" void kernel_launch(void* const* d_in, const int* in_sizes, int n_in,
                              void* d_out, int out_size)
{
    const float* x  = (const float*)d_in[0];
    const float* Wq = (const float*)d_in[1];
    const float* bq = (const float*)d_in[2];
    const float* Wk = (const float*)d_in[3];
    const float* bk = (const float*)d_in[4];
    const float* Wv = (const float*)d_in[5];
    const float* bv = (const float*)d_in[6];
    const float* pb = (const float*)d_in[7];
    float* out = (float*)d_out;

    __half *Ax, *Bqk, *Bv, *Qe, *Ke, *Vt, *P;
    float *b2, *V, *Sm;
    cudaGetSymbolAddress((void**)&Ax,  g_Ax);
    cudaGetSymbolAddress((void**)&Bqk, g_Bqk);
    cudaGetSymbolAddress((void**)&Bv,  g_Bv);
    cudaGetSymbolAddress((void**)&b2,  g_bqk);
    cudaGetSymbolAddress((void**)&V,   g_V);
    cudaGetSymbolAddress((void**)&Qe,  g_Qe);
    cudaGetSymbolAddress((void**)&Ke,  g_Ke);
    cudaGetSymbolAddress((void**)&Vt,  g_Vt);
    cudaGetSymbolAddress((void**)&Sm,  g_S);
    cudaGetSymbolAddress((void**)&P,   g_P);

    cudaFuncSetAttribute(hgemm_nt<EPI_STORE>,
                         cudaFuncAttributeMaxDynamicSharedMemorySize,
                         H_SMEM_BYTES);
    cudaFuncSetAttribute(hgemm_nt<EPI_THETA>,
                         cudaFuncAttributeMaxDynamicSharedMemorySize,
                         H_SMEM_BYTES);

    // 0) build fp16 operands
    convert_x<<<(MTOT * DIM) / 256, 256>>>(x, Ax);
    convert_w<<<(DIM * DIM) / 256, 256>>>(Wq, Wk, Wv, Bqk, Bv);
    concat_bias<<<DE / 256, 256>>>(bq, bk, b2);

    // 1) QK projection (split2, K=3072) with fused theta epilogue -> Qe, Ke
    dim3 gQK(DE / 128, MTOT / 128, 1);
    hgemm_nt<EPI_THETA><<<gQK, 128, H_SMEM_BYTES>>>(
        Ax, Bqk, b2, nullptr, Qe, Ke, pb,
        DE, KQK, KQK, KQK, 0, 0, 0);

    // 2) V projection (plain fp16, K=1024) -> V fp32
    dim3 gV(DIM / 128, MTOT / 128, 1);
    hgemm_nt<EPI_STORE><<<gV, 128, H_SMEM_BYTES>>>(
        Ax, Bv, bv, V, nullptr, nullptr, nullptr,
        DIM, DIM, KQK, DIM, 0, 0, 0);

    // 3) V transpose -> fp16 [DIM][SEQ] per batch
    dim3 gT(DIM / 32, SEQ / 32, BATCH);
    transpose_v<<<gT, dim3(32, 8)>>>(V, Vt);

    // 4) sim = Qe @ Ke^T per batch (fp16 mma k16)
    dim3 gSim(SEQ / 128, SEQ / 128, BATCH);
    hgemm_nt<EPI_STORE><<<gSim, 128, H_SMEM_BYTES>>>(
        Qe, Ke, nullptr, Sm, nullptr, nullptr, nullptr,
        SEQ, DE, DE, DE,
        (size_t)SEQ * DE, (size_t)SEQ * DE, (size_t)SEQ * SEQ);

    // 5) softmax(sim / 32) rows -> fp16 weights
    softmax_rows<<<BATCH * SEQ, 256>>>(Sm, P);

    // 6) out = P @ Vt^T per batch (fp16 mma k16)
    dim3 gPV(DIM / 128, SEQ / 128, BATCH);
    hgemm_nt<EPI_STORE><<<gPV, 128, H_SMEM_BYTES>>>(
        P, Vt, nullptr, out, nullptr, nullptr, nullptr,
        DIM, SEQ, SEQ, SEQ,
        (size_t)SEQ * SEQ, (size_t)DIM * SEQ, (size_t)SEQ * DIM);
}

// round 14
// speedup vs baseline: 1.2461x; 1.1535x over previous
#include <cuda_runtime.h>
#include <cuda_fp16.h>
#include <math.h>
#include <stdint.h>

// Problem sizes (fixed)
#define BATCH 2
#define SEQ   4096
#define DIM   1024
#define MTOT  (BATCH * SEQ)     // 8192
#define DE    (2 * DIM)         // 2048  (cos || sin concatenated)
#define KQK   (3 * DIM)         // 3072  (split2 K for QK projection)

// ---------------- scratch (device globals; no allocation allowed) ----------
__device__ __half g_Ax [(size_t)MTOT * KQK];           // [8192][3072] = [xh|xh|xl]
__device__ __half g_Bqk[(size_t)DE * KQK];             // [2048][3072]: Wq/Wk rows [Wh|Wl|Wh]
__device__ __half g_Bv [(size_t)DIM * DIM];            // [1024][1024]: Wv fp16
__device__ float  g_bqk[DE];                           // bq | bk
__device__ __half g_Qe [(size_t)MTOT * DE];            // [8192][2048] = [cos|sin]
__device__ __half g_Ke [(size_t)MTOT * DE];
__device__ __half g_Vt [(size_t)MTOT * DIM];           // per batch [DIM][SEQ]
__device__ float  g_S  [(size_t)BATCH * SEQ * SEQ];    // scores fp32 (134 MB)
__device__ __half g_P  [(size_t)BATCH * SEQ * SEQ];    // weights fp16 (67 MB)

// ============================ helpers =======================================
__device__ __forceinline__ uint32_t smem_u32(const void* p) {
    uint32_t a;
    asm("{ .reg .u64 t; cvta.to.shared.u64 t, %1; cvt.u32.u64 %0, t; }"
        : "=r"(a) : "l"(p));
    return a;
}

__device__ __forceinline__ void cpasync16(uint32_t saddr, const void* gaddr) {
    asm volatile("cp.async.cg.shared.global [%0], [%1], 16;"
                 :: "r"(saddr), "l"(gaddr) : "memory");
}

__device__ __forceinline__ void ldsm_x4(uint32_t r[4], uint32_t addr) {
    asm volatile("ldmatrix.sync.aligned.m8n8.x4.shared.b16 {%0,%1,%2,%3}, [%4];"
                 : "=r"(r[0]), "=r"(r[1]), "=r"(r[2]), "=r"(r[3])
                 : "r"(addr));
}

__device__ __forceinline__ void mma_f16(float c[4], const uint32_t a[4],
                                        const uint32_t b[2]) {
    asm volatile(
        "mma.sync.aligned.m16n8k16.row.col.f32.f16.f16.f32 "
        "{%0,%1,%2,%3}, {%4,%5,%6,%7}, {%8,%9}, {%0,%1,%2,%3};"
        : "+f"(c[0]), "+f"(c[1]), "+f"(c[2]), "+f"(c[3])
        : "r"(a[0]), "r"(a[1]), "r"(a[2]), "r"(a[3]),
          "r"(b[0]), "r"(b[1]));
}

#define EPI_STORE 0   // fp32 C (+bias)
#define EPI_THETA 1   // QK projection: sincos(Q*inv_wl + pb) -> Qe/Ke fp16
#define EPI_VT    2   // V projection: write fp16 transposed into Vt[b][n][s]

// ============================================================================
// fp16 tensor-core NT GEMM via mma.sync.m16n8k16 (PROVEN R11 CONFIG):
//   acc[M,N] = A[M,K] @ B[N,K]^T, fp32 accumulate.
// 128x128 CTA tile, k-tile 64 halfs, 3-stage cp.async ring, 256 threads
// (8 warps, 2x4, warp tile 64x32), 144B-padded rows (conflict-free ldmatrix),
// fragment double-buffering, one barrier per k-tile, 2 CTAs/SM.
// M%128==0, N%128==0, K%64==0.
// ============================================================================
#define H_STAGE_BYTES  36864              // 2 * 128 rows * 144 B
#define H_SMEM_BYTES   (3 * H_STAGE_BYTES)

template<int EPI>
__global__ void __launch_bounds__(256, 2)
hgemm_nt(const __half* __restrict__ A, const __half* __restrict__ B,
         const float* __restrict__ bias, float* __restrict__ C,
         __half* __restrict__ Qe, __half* __restrict__ Ke,
         const float* __restrict__ pb,
         int Nld, int K, int lda, int ldb,
         size_t strA, size_t strB, size_t strC)
{
    extern __shared__ float dynsmem[];
    const uint32_t sb = smem_u32(dynsmem);

    const int tid  = threadIdx.x;
    const int wid  = tid >> 5;
    const int lane = tid & 31;

    A += strA * blockIdx.z;
    B += strB * blockIdx.z;
    C += strC * blockIdx.z;
    const int tileM = blockIdx.y * 128;
    const int tileN = blockIdx.x * 128;

    // ---- loader: thread covers rows baseRow + 32*i (i<4), 16B seg of 128B row
    const int baseRow = tid >> 3;      // 0..31
    const int seg     = tid & 7;       // 0..7
    const __half* Ath = A + (size_t)(tileM + baseRow) * lda + seg * 8;
    const __half* Bth = B + (size_t)(tileN + baseRow) * ldb + seg * 8;
    const uint32_t thoff = (uint32_t)(baseRow * 144 + seg * 16);

#define ISSUE_STAGE(KT, S) do {                                               \
    uint32_t _sa = sb + (uint32_t)(S) * H_STAGE_BYTES + thoff;                \
    const __half* _ga = Ath + (size_t)(KT) * 64;                              \
    const __half* _gb = Bth + (size_t)(KT) * 64;                              \
    _Pragma("unroll")                                                         \
    for (int _i = 0; _i < 4; _i++)                                            \
        cpasync16(_sa + _i * (32u * 144u), _ga + (size_t)_i * 32 * lda);      \
    _Pragma("unroll")                                                         \
    for (int _i = 0; _i < 4; _i++)                                            \
        cpasync16(_sa + 18432u + _i * (32u * 144u), _gb + (size_t)_i * 32 * ldb); \
    asm volatile("cp.async.commit_group;" ::: "memory");                      \
} while (0)

    const int nkt = K >> 6;            // 64 halfs per k-tile
    ISSUE_STAGE(0, 0);
    ISSUE_STAGE(1, 1);

    // ---- compute mapping
    const int warp_m = wid >> 2;       // 0..1  -> 64 rows
    const int warp_n = wid & 3;        // 0..3  -> 32 cols
    const int g   = lane >> 2;         // 0..7
    const int tig = lane & 3;          // 0..3

    const uint32_t laneA = (uint32_t)((lane & 15) * 144 + (lane >> 4) * 16);
    const uint32_t laneB = (uint32_t)(((lane & 7) + ((lane >> 4) & 1) * 8) * 144
                                      + ((lane >> 3) & 1) * 16);

#define LOAD_FRAGS(BUF, KS) do {                                              \
    uint32_t t0[4], t1[4];                                                    \
    _Pragma("unroll")                                                         \
    for (int _mi = 0; _mi < 4; _mi++)                                         \
        ldsm_x4(afr[BUF][_mi], aBase + _mi * 2304u + (KS) * 32u);             \
    ldsm_x4(t0, bBase + (KS) * 32u);                                          \
    ldsm_x4(t1, bBase + 2304u + (KS) * 32u);                                  \
    bfr[BUF][0][0] = t0[0]; bfr[BUF][0][1] = t0[1];                           \
    bfr[BUF][1][0] = t0[2]; bfr[BUF][1][1] = t0[3];                           \
    bfr[BUF][2][0] = t1[0]; bfr[BUF][2][1] = t1[1];                           \
    bfr[BUF][3][0] = t1[2]; bfr[BUF][3][1] = t1[3];                           \
} while (0)

    float acc[4][4][4];
#pragma unroll
    for (int mi = 0; mi < 4; mi++)
#pragma unroll
        for (int nj = 0; nj < 4; nj++)
#pragma unroll
            for (int r = 0; r < 4; r++) acc[mi][nj][r] = 0.0f;

    int s = 0;   // stage of tile kt
    for (int kt = 0; kt < nkt; ++kt) {
        if (kt + 2 < nkt) {
            asm volatile("cp.async.wait_group 1;" ::: "memory");
        } else {
            asm volatile("cp.async.wait_group 0;" ::: "memory");
        }
        __syncthreads();   // tile kt visible + all warps done with kt-1's stage

        if (kt + 2 < nkt) {
            const int s2 = (s + 2 >= 3) ? (s - 1) : (s + 2);
            ISSUE_STAGE(kt + 2, s2);
        }

        const uint32_t stAddr = sb + (uint32_t)s * H_STAGE_BYTES;
        const uint32_t aBase = stAddr + (uint32_t)(warp_m * 64) * 144 + laneA;
        const uint32_t bBase = stAddr + 18432u + (uint32_t)(warp_n * 32) * 144 + laneB;

        uint32_t afr[2][4][4];
        uint32_t bfr[2][4][2];
        LOAD_FRAGS(0, 0);

#pragma unroll
        for (int ks = 0; ks < 4; ++ks) {
            const int cur = ks & 1;
            if (ks < 3) LOAD_FRAGS(cur ^ 1, ks + 1);
#pragma unroll
            for (int mi = 0; mi < 4; mi++)
#pragma unroll
                for (int nj = 0; nj < 4; nj++)
                    mma_f16(acc[mi][nj], afr[cur][mi], bfr[cur][nj]);
        }
        s = (s + 1 == 3) ? 0 : (s + 1);
    }
#undef ISSUE_STAGE
#undef LOAD_FRAGS

    if (EPI == EPI_STORE) {
#pragma unroll
        for (int mi = 0; mi < 4; mi++) {
            const int row0 = tileM + warp_m * 64 + mi * 16 + g;
#pragma unroll
            for (int nj = 0; nj < 4; nj++) {
                const int col = tileN + warp_n * 32 + nj * 8 + 2 * tig;
                float2 bv = {0.0f, 0.0f};
                if (bias) bv = *(const float2*)(bias + col);
                float2 lo = { acc[mi][nj][0] + bv.x, acc[mi][nj][1] + bv.y };
                float2 hi = { acc[mi][nj][2] + bv.x, acc[mi][nj][3] + bv.y };
                *(float2*)(C + (size_t)row0 * Nld + col)       = lo;
                *(float2*)(C + (size_t)(row0 + 8) * Nld + col) = hi;
            }
        }
    } else if (EPI == EPI_THETA) {
        // acc = Q or K pre-bias, fp32-exact. col<1024 -> Qe col d; else Ke.
        const float WLC = (float)(6.283185307179586 / (double)DIM);
#pragma unroll
        for (int mi = 0; mi < 4; mi++) {
            const int row0 = tileM + warp_m * 64 + mi * 16 + g;
#pragma unroll
            for (int nj = 0; nj < 4; nj++) {
                const int col = tileN + warp_n * 32 + nj * 8 + 2 * tig;
                const int d   = col & (DIM - 1);
                __half* dst = (col < DIM) ? Qe : Ke;
                float2 bv = *(const float2*)(bias + col);
                float inv0 = 1.0f / ((float)(d + 1) * WLC + 1e-8f);
                float inv1 = 1.0f / ((float)(d + 2) * WLC + 1e-8f);
                float p0 = pb[d], p1 = pb[d + 1];
#pragma unroll
                for (int h = 0; h < 2; h++) {       // rows row0, row0+8
                    const int row = row0 + 8 * h;
                    float q0 = acc[mi][nj][2 * h + 0] + bv.x;
                    float q1 = acc[mi][nj][2 * h + 1] + bv.y;
                    float s0, c0, s1, c1;
                    sincosf(fmaf(q0, inv0, p0), &s0, &c0);
                    sincosf(fmaf(q1, inv1, p1), &s1, &c1);
                    __half* base = dst + (size_t)row * DE + d;
                    *(__half2*)(base)       = __floats2half2_rn(c0, c1);
                    *(__half2*)(base + DIM) = __floats2half2_rn(s0, s1);
                }
            }
        }
    } else {
        // EPI_VT: V projection; write fp16 TRANSPOSED into Vt[b][col][s].
        // row (global m) -> b = row>>12, s = row & 4095. Qe reused as Vt ptr.
        __half* Vt = Qe;
#pragma unroll
        for (int mi = 0; mi < 4; mi++) {
            const int row0 = tileM + warp_m * 64 + mi * 16 + g;
#pragma unroll
            for (int nj = 0; nj < 4; nj++) {
                const int col = tileN + warp_n * 32 + nj * 8 + 2 * tig;
                float2 bv = *(const float2*)(bias + col);
#pragma unroll
                for (int h = 0; h < 2; h++) {
                    const int row = row0 + 8 * h;
                    const int b   = row >> 12;
                    const int sIx = row & (SEQ - 1);
                    float v0 = acc[mi][nj][2 * h + 0] + bv.x;
                    float v1 = acc[mi][nj][2 * h + 1] + bv.y;
                    __half* vb = Vt + (size_t)b * DIM * SEQ + sIx;
                    vb[(size_t)col * SEQ]       = __float2half_rn(v0);
                    vb[(size_t)(col + 1) * SEQ] = __float2half_rn(v1);
                }
            }
        }
    }
}

// ---------------------------------------------------------------------------
// prep: fp16 split2 operands.
// A' = [xh | xh | xl]; Bqk rows (Wq then Wk): [Wh | Wl | Wh]; Bv = Wv fp16.
// ---------------------------------------------------------------------------
__global__ void __launch_bounds__(256)
convert_x(const float* __restrict__ x, __half* __restrict__ Ax)
{
    const int idx = blockIdx.x * blockDim.x + threadIdx.x;   // < MTOT*DIM
    const int m = idx >> 10;
    const int d = idx & (DIM - 1);
    float v = x[idx];
    __half h = __float2half_rn(v);
    __half l = __float2half_rn(v - __half2float(h));
    size_t base = (size_t)m * KQK;
    Ax[base + d]            = h;
    Ax[base + DIM + d]      = h;
    Ax[base + 2 * DIM + d]  = l;
}

__global__ void __launch_bounds__(256)
convert_w(const float* __restrict__ Wq, const float* __restrict__ Wk,
          const float* __restrict__ Wv,
          __half* __restrict__ Bqk, __half* __restrict__ Bv)
{
    const int idx = blockIdx.x * blockDim.x + threadIdx.x;   // < DIM*DIM
    const int n = idx >> 10;
    const int k = idx & (DIM - 1);
    {
        float v = Wq[idx];
        __half h = __float2half_rn(v);
        __half l = __float2half_rn(v - __half2float(h));
        size_t base = (size_t)n * KQK;
        Bqk[base + k]           = h;
        Bqk[base + DIM + k]     = l;
        Bqk[base + 2 * DIM + k] = h;
    }
    {
        float v = Wk[idx];
        __half h = __float2half_rn(v);
        __half l = __float2half_rn(v - __half2float(h));
        size_t base = (size_t)(DIM + n) * KQK;
        Bqk[base + k]           = h;
        Bqk[base + DIM + k]     = l;
        Bqk[base + 2 * DIM + k] = h;
    }
    Bv[idx] = __float2half_rn(Wv[idx]);
}

__global__ void __launch_bounds__(256)
concat_bias(const float* __restrict__ bq, const float* __restrict__ bk,
            float* __restrict__ b2)
{
    const int i = blockIdx.x * blockDim.x + threadIdx.x;     // < DE
    b2[i] = (i < DIM) ? bq[i] : bk[i - DIM];
}

// ---------------------------------------------------------------------------
// softmax rows (len SEQ), logits /32; writes fp16 weights to P.
// ---------------------------------------------------------------------------
__global__ void __launch_bounds__(256)
softmax_rows(const float* __restrict__ S, __half* __restrict__ P)
{
    __shared__ float sm[8];
    const float* p = S + (size_t)blockIdx.x * SEQ;
    __half* po = P + (size_t)blockIdx.x * SEQ;
    const float4* p4 = (const float4*)p;
    const int t    = threadIdx.x;
    const int lane = t & 31;
    const int wid  = t >> 5;
    const float SCALE = 0.03125f;   // 1/sqrt(1024)

    float v[16];
    float mx = -1e30f;
#pragma unroll
    for (int i = 0; i < 4; i++) {
        float4 x = p4[t + i * 256];
        v[4*i+0] = x.x * SCALE; v[4*i+1] = x.y * SCALE;
        v[4*i+2] = x.z * SCALE; v[4*i+3] = x.w * SCALE;
        mx = fmaxf(mx, fmaxf(fmaxf(v[4*i+0], v[4*i+1]),
                             fmaxf(v[4*i+2], v[4*i+3])));
    }
#pragma unroll
    for (int off = 16; off >= 1; off >>= 1)
        mx = fmaxf(mx, __shfl_xor_sync(0xffffffffu, mx, off));
    if (lane == 0) sm[wid] = mx;
    __syncthreads();
    mx = sm[0];
#pragma unroll
    for (int w = 1; w < 8; w++) mx = fmaxf(mx, sm[w]);
    __syncthreads();

    float sum = 0.0f;
#pragma unroll
    for (int i = 0; i < 16; i++) { v[i] = expf(v[i] - mx); sum += v[i]; }
#pragma unroll
    for (int off = 16; off >= 1; off >>= 1)
        sum += __shfl_xor_sync(0xffffffffu, sum, off);
    if (lane == 0) sm[wid] = sum;
    __syncthreads();
    sum = sm[0];
#pragma unroll
    for (int w = 1; w < 8; w++) sum += sm[w];
    float inv = 1.0f / sum;

    __half2* po2 = (__half2*)po;
#pragma unroll
    for (int i = 0; i < 4; i++) {
        const int e = 4 * (t + i * 256);
        po2[e / 2]     = __floats2half2_rn(v[4*i+0] * inv, v[4*i+1] * inv);
        po2[e / 2 + 1] = __floats2half2_rn(v[4*i+2] * inv, v[4*i+3] * inv);
    }
}

// ---------------------------------------------------------------------------
extern "C" void kernel_launch(void* const* d_in, const int* in_sizes, int n_in,
                              void* d_out, int out_size)
{
    const float* x  = (const float*)d_in[0];
    const float* Wq = (const float*)d_in[1];
    const float* bq = (const float*)d_in[2];
    const float* Wk = (const float*)d_in[3];
    const float* bk = (const float*)d_in[4];
    const float* Wv = (const float*)d_in[5];
    const float* bv = (const float*)d_in[6];
    const float* pb = (const float*)d_in[7];
    float* out = (float*)d_out;

    __half *Ax, *Bqk, *Bv, *Qe, *Ke, *Vt, *P;
    float *b2, *Sm;
    cudaGetSymbolAddress((void**)&Ax,  g_Ax);
    cudaGetSymbolAddress((void**)&Bqk, g_Bqk);
    cudaGetSymbolAddress((void**)&Bv,  g_Bv);
    cudaGetSymbolAddress((void**)&b2,  g_bqk);
    cudaGetSymbolAddress((void**)&Qe,  g_Qe);
    cudaGetSymbolAddress((void**)&Ke,  g_Ke);
    cudaGetSymbolAddress((void**)&Vt,  g_Vt);
    cudaGetSymbolAddress((void**)&Sm,  g_S);
    cudaGetSymbolAddress((void**)&P,   g_P);

    cudaFuncSetAttribute(hgemm_nt<EPI_STORE>,
                         cudaFuncAttributeMaxDynamicSharedMemorySize,
                         H_SMEM_BYTES);
    cudaFuncSetAttribute(hgemm_nt<EPI_THETA>,
                         cudaFuncAttributeMaxDynamicSharedMemorySize,
                         H_SMEM_BYTES);
    cudaFuncSetAttribute(hgemm_nt<EPI_VT>,
                         cudaFuncAttributeMaxDynamicSharedMemorySize,
                         H_SMEM_BYTES);

    // 0) build fp16 operands
    convert_x<<<(MTOT * DIM) / 256, 256>>>(x, Ax);
    convert_w<<<(DIM * DIM) / 256, 256>>>(Wq, Wk, Wv, Bqk, Bv);
    concat_bias<<<DE / 256, 256>>>(bq, bk, b2);

    // 1) QK projection (split2, K=3072) with fused theta epilogue -> Qe, Ke
    dim3 gQK(DE / 128, MTOT / 128, 1);
    hgemm_nt<EPI_THETA><<<gQK, 256, H_SMEM_BYTES>>>(
        Ax, Bqk, b2, nullptr, Qe, Ke, pb,
        DE, KQK, KQK, KQK, 0, 0, 0);

    // 2) V projection (plain fp16, K=1024) with fused transpose -> Vt fp16
    dim3 gV(DIM / 128, MTOT / 128, 1);
    hgemm_nt<EPI_VT><<<gV, 256, H_SMEM_BYTES>>>(
        Ax, Bv, bv, nullptr, Vt, nullptr, nullptr,
        DIM, DIM, KQK, DIM, 0, 0, 0);

    // 3) sim = Qe @ Ke^T per batch (fp16 mma k16)
    dim3 gSim(SEQ / 128, SEQ / 128, BATCH);
    hgemm_nt<EPI_STORE><<<gSim, 256, H_SMEM_BYTES>>>(
        Qe, Ke, nullptr, Sm, nullptr, nullptr, nullptr,
        SEQ, DE, DE, DE,
        (size_t)SEQ * DE, (size_t)SEQ * DE, (size_t)SEQ * SEQ);

    // 4) softmax(sim / 32) rows -> fp16 weights
    softmax_rows<<<BATCH * SEQ, 256>>>(Sm, P);

    // 5) out = P @ Vt^T per batch (fp16 mma k16)
    dim3 gPV(DIM / 128, SEQ / 128, BATCH);
    hgemm_nt<EPI_STORE><<<gPV, 256, H_SMEM_BYTES>>>(
        P, Vt, nullptr, out, nullptr, nullptr, nullptr,
        DIM, SEQ, SEQ, SEQ,
        (size_t)SEQ * SEQ, (size_t)DIM * SEQ, (size_t)SEQ * DIM);
}

// round 16
// speedup vs baseline: 1.2513x; 1.0042x over previous
#include <cuda_runtime.h>
#include <cuda_fp16.h>
#include <math.h>
#include <stdint.h>

// Problem sizes (fixed)
#define BATCH 2
#define SEQ   4096
#define DIM   1024
#define MTOT  (BATCH * SEQ)     // 8192
#define DE    (2 * DIM)         // 2048  (cos || sin concatenated)
#define KQK   (3 * DIM)         // 3072  (split2 K for QK projection)

// ---------------- scratch (device globals; no allocation allowed) ----------
__device__ __half g_Ax [(size_t)MTOT * KQK];           // [8192][3072] = [xh|xh|xl]
__device__ __half g_Bqk[(size_t)DE * KQK];             // [2048][3072]: Wq/Wk rows [Wh|Wl|Wh]
__device__ __half g_Bv [(size_t)DIM * DIM];            // [1024][1024]: Wv fp16
__device__ float  g_bqk[DE];                           // bq | bk
__device__ __half g_Qe [(size_t)MTOT * DE];            // [8192][2048] = [cos|sin]
__device__ __half g_Ke [(size_t)MTOT * DE];
__device__ __half g_Vt [(size_t)MTOT * DIM];           // per batch [DIM][SEQ]
__device__ float  g_S  [(size_t)BATCH * SEQ * SEQ];    // logits fp32, pre-scaled (134 MB)
__device__ __half g_P  [(size_t)BATCH * SEQ * SEQ];    // weights fp16 (67 MB)

// ============================ helpers =======================================
__device__ __forceinline__ uint32_t smem_u32(const void* p) {
    uint32_t a;
    asm("{ .reg .u64 t; cvta.to.shared.u64 t, %1; cvt.u32.u64 %0, t; }"
        : "=r"(a) : "l"(p));
    return a;
}

__device__ __forceinline__ void cpasync16(uint32_t saddr, const void* gaddr) {
    asm volatile("cp.async.cg.shared.global [%0], [%1], 16;"
                 :: "r"(saddr), "l"(gaddr) : "memory");
}

__device__ __forceinline__ void ldsm_x4(uint32_t r[4], uint32_t addr) {
    asm volatile("ldmatrix.sync.aligned.m8n8.x4.shared.b16 {%0,%1,%2,%3}, [%4];"
                 : "=r"(r[0]), "=r"(r[1]), "=r"(r[2]), "=r"(r[3])
                 : "r"(addr));
}

__device__ __forceinline__ void mma_f16(float c[4], const uint32_t a[4],
                                        const uint32_t b[2]) {
    asm volatile(
        "mma.sync.aligned.m16n8k16.row.col.f32.f16.f16.f32 "
        "{%0,%1,%2,%3}, {%4,%5,%6,%7}, {%8,%9}, {%0,%1,%2,%3};"
        : "+f"(c[0]), "+f"(c[1]), "+f"(c[2]), "+f"(c[3])
        : "r"(a[0]), "r"(a[1]), "r"(a[2]), "r"(a[3]),
          "r"(b[0]), "r"(b[1]));
}

#define EPI_STORE 0   // fp32 C (+bias)   (PV output)
#define EPI_THETA 1   // QK projection: sincos(Q*inv_wl + pb) -> Qe/Ke fp16
#define EPI_VT    2   // V projection: smem-staged transpose -> Vt[b][n][s] fp16
#define EPI_SIM   3   // sim: fp32 logits * (1/32) into S

// ============================================================================
// fp16 tensor-core NT GEMM via mma.sync.m16n8k16 (PROVEN R11 CONFIG):
//   acc[M,N] = A[M,K] @ B[N,K]^T, fp32 accumulate.
// 128x128 CTA tile, k-tile 64 halfs, 3-stage cp.async ring, 256 threads
// (8 warps, 2x4, warp tile 64x32), 144B-padded rows (conflict-free ldmatrix),
// fragment double-buffering + head-start, one barrier per k-tile, 2 CTAs/SM.
// M%128==0, N%128==0, K%64==0.
// ============================================================================
#define H_STAGE_BYTES  36864              // 2 * 128 rows * 144 B
#define H_SMEM_BYTES   (3 * H_STAGE_BYTES)

template<int EPI>
__global__ void __launch_bounds__(256, 2)
hgemm_nt(const __half* __restrict__ A, const __half* __restrict__ B,
         const float* __restrict__ bias, float* __restrict__ C,
         __half* __restrict__ Qe, __half* __restrict__ Ke,
         const float* __restrict__ pb,
         int Nld, int K, int lda, int ldb,
         size_t strA, size_t strB, size_t strC)
{
    extern __shared__ float dynsmem[];
    const uint32_t sb = smem_u32(dynsmem);

    const int tid  = threadIdx.x;
    const int wid  = tid >> 5;
    const int lane = tid & 31;

    A += strA * blockIdx.z;
    B += strB * blockIdx.z;
    C += strC * blockIdx.z;
    const int tileM = blockIdx.y * 128;
    const int tileN = blockIdx.x * 128;

    // ---- loader: thread covers rows baseRow + 32*i (i<4), 16B seg of 128B row
    const int baseRow = tid >> 3;      // 0..31
    const int seg     = tid & 7;       // 0..7
    const __half* Ath = A + (size_t)(tileM + baseRow) * lda + seg * 8;
    const __half* Bth = B + (size_t)(tileN + baseRow) * ldb + seg * 8;
    const uint32_t thoff = (uint32_t)(baseRow * 144 + seg * 16);

#define ISSUE_STAGE(KT, S) do {                                               \
    uint32_t _sa = sb + (uint32_t)(S) * H_STAGE_BYTES + thoff;                \
    const __half* _ga = Ath + (size_t)(KT) * 64;                              \
    const __half* _gb = Bth + (size_t)(KT) * 64;                              \
    _Pragma("unroll")                                                         \
    for (int _i = 0; _i < 4; _i++)                                            \
        cpasync16(_sa + _i * (32u * 144u), _ga + (size_t)_i * 32 * lda);      \
    _Pragma("unroll")                                                         \
    for (int _i = 0; _i < 4; _i++)                                            \
        cpasync16(_sa + 18432u + _i * (32u * 144u), _gb + (size_t)_i * 32 * ldb); \
    asm volatile("cp.async.commit_group;" ::: "memory");                      \
} while (0)

    const int nkt = K >> 6;            // 64 halfs per k-tile
    ISSUE_STAGE(0, 0);
    ISSUE_STAGE(1, 1);

    // ---- compute mapping
    const int warp_m = wid >> 2;       // 0..1  -> 64 rows
    const int warp_n = wid & 3;        // 0..3  -> 32 cols
    const int g   = lane >> 2;         // 0..7
    const int tig = lane & 3;          // 0..3

    const uint32_t laneA = (uint32_t)((lane & 15) * 144 + (lane >> 4) * 16);
    const uint32_t laneB = (uint32_t)(((lane & 7) + ((lane >> 4) & 1) * 8) * 144
                                      + ((lane >> 3) & 1) * 16);

#define LOAD_FRAGS(BUF, KS) do {                                              \
    uint32_t t0[4], t1[4];                                                    \
    _Pragma("unroll")                                                         \
    for (int _mi = 0; _mi < 4; _mi++)                                         \
        ldsm_x4(afr[BUF][_mi], aBase + _mi * 2304u + (KS) * 32u);             \
    ldsm_x4(t0, bBase + (KS) * 32u);                                          \
    ldsm_x4(t1, bBase + 2304u + (KS) * 32u);                                  \
    bfr[BUF][0][0] = t0[0]; bfr[BUF][0][1] = t0[1];                           \
    bfr[BUF][1][0] = t0[2]; bfr[BUF][1][1] = t0[3];                           \
    bfr[BUF][2][0] = t1[0]; bfr[BUF][2][1] = t1[1];                           \
    bfr[BUF][3][0] = t1[2]; bfr[BUF][3][1] = t1[3];                           \
} while (0)

    float acc[4][4][4];
#pragma unroll
    for (int mi = 0; mi < 4; mi++)
#pragma unroll
        for (int nj = 0; nj < 4; nj++)
#pragma unroll
            for (int r = 0; r < 4; r++) acc[mi][nj][r] = 0.0f;

    int s = 0;   // stage of tile kt
    for (int kt = 0; kt < nkt; ++kt) {
        if (kt + 2 < nkt) {
            asm volatile("cp.async.wait_group 1;" ::: "memory");
        } else {
            asm volatile("cp.async.wait_group 0;" ::: "memory");
        }
        __syncthreads();   // tile kt visible + all warps done with kt-1's stage

        const uint32_t stAddr = sb + (uint32_t)s * H_STAGE_BYTES;
        const uint32_t aBase = stAddr + (uint32_t)(warp_m * 64) * 144 + laneA;
        const uint32_t bBase = stAddr + 18432u + (uint32_t)(warp_n * 32) * 144 + laneB;

        uint32_t afr[2][4][4];
        uint32_t bfr[2][4][2];
        LOAD_FRAGS(0, 0);      // head-start: overlaps with cp.async issue below

        if (kt + 2 < nkt) {
            const int s2 = (s + 2 >= 3) ? (s - 1) : (s + 2);
            ISSUE_STAGE(kt + 2, s2);
        }

#pragma unroll
        for (int ks = 0; ks < 4; ++ks) {
            const int cur = ks & 1;
            if (ks < 3) LOAD_FRAGS(cur ^ 1, ks + 1);
#pragma unroll
            for (int mi = 0; mi < 4; mi++)
#pragma unroll
                for (int nj = 0; nj < 4; nj++)
                    mma_f16(acc[mi][nj], afr[cur][mi], bfr[cur][nj]);
        }
        s = (s + 1 == 3) ? 0 : (s + 1);
    }
#undef ISSUE_STAGE
#undef LOAD_FRAGS

    if (EPI == EPI_STORE) {
#pragma unroll
        for (int mi = 0; mi < 4; mi++) {
            const int row0 = tileM + warp_m * 64 + mi * 16 + g;
#pragma unroll
            for (int nj = 0; nj < 4; nj++) {
                const int col = tileN + warp_n * 32 + nj * 8 + 2 * tig;
                float2 bv = {0.0f, 0.0f};
                if (bias) bv = *(const float2*)(bias + col);
                float2 lo = { acc[mi][nj][0] + bv.x, acc[mi][nj][1] + bv.y };
                float2 hi = { acc[mi][nj][2] + bv.x, acc[mi][nj][3] + bv.y };
                *(float2*)(C + (size_t)row0 * Nld + col)       = lo;
                *(float2*)(C + (size_t)(row0 + 8) * Nld + col) = hi;
            }
        }
    } else if (EPI == EPI_SIM) {
        // fp32 logits scaled by 1/sqrt(DIM)
        const float SC = 0.03125f;
#pragma unroll
        for (int mi = 0; mi < 4; mi++) {
            const int row0 = tileM + warp_m * 64 + mi * 16 + g;
#pragma unroll
            for (int nj = 0; nj < 4; nj++) {
                const int col = tileN + warp_n * 32 + nj * 8 + 2 * tig;
                float2 lo = { acc[mi][nj][0] * SC, acc[mi][nj][1] * SC };
                float2 hi = { acc[mi][nj][2] * SC, acc[mi][nj][3] * SC };
                *(float2*)(C + (size_t)row0 * Nld + col)       = lo;
                *(float2*)(C + (size_t)(row0 + 8) * Nld + col) = hi;
            }
        }
    } else if (EPI == EPI_THETA) {
        // acc = Q or K pre-bias, fp32-exact. col<1024 -> Qe col d; else Ke.
        const float WLC = (float)(6.283185307179586 / (double)DIM);
#pragma unroll
        for (int mi = 0; mi < 4; mi++) {
            const int row0 = tileM + warp_m * 64 + mi * 16 + g;
#pragma unroll
            for (int nj = 0; nj < 4; nj++) {
                const int col = tileN + warp_n * 32 + nj * 8 + 2 * tig;
                const int d   = col & (DIM - 1);
                __half* dst = (col < DIM) ? Qe : Ke;
                float2 bv = *(const float2*)(bias + col);
                float inv0 = 1.0f / ((float)(d + 1) * WLC + 1e-8f);
                float inv1 = 1.0f / ((float)(d + 2) * WLC + 1e-8f);
                float p0 = pb[d], p1 = pb[d + 1];
#pragma unroll
                for (int h = 0; h < 2; h++) {       // rows row0, row0+8
                    const int row = row0 + 8 * h;
                    float q0 = acc[mi][nj][2 * h + 0] + bv.x;
                    float q1 = acc[mi][nj][2 * h + 1] + bv.y;
                    float s0, c0, s1, c1;
                    sincosf(fmaf(q0, inv0, p0), &s0, &c0);
                    sincosf(fmaf(q1, inv1, p1), &s1, &c1);
                    __half* base = dst + (size_t)row * DE + d;
                    *(__half2*)(base)       = __floats2half2_rn(c0, c1);
                    *(__half2*)(base + DIM) = __floats2half2_rn(s0, s1);
                }
            }
        }
    } else {
        // EPI_VT: V projection; smem-staged transpose then coalesced stores.
        // smem layout: st[col][row] halfs, row-padded stride 132.
        __syncthreads();                      // done with pipeline smem
        __half* st = (__half*)dynsmem;
#pragma unroll
        for (int mi = 0; mi < 4; mi++) {
            const int rloc = warp_m * 64 + mi * 16 + g;   // tile-local row
#pragma unroll
            for (int nj = 0; nj < 4; nj++) {
                const int cloc = warp_n * 32 + nj * 8 + 2 * tig;
                float2 bv = *(const float2*)(bias + tileN + cloc);
#pragma unroll
                for (int h = 0; h < 2; h++) {
                    const int r = rloc + 8 * h;
                    st[(size_t)cloc * 132 + r]       =
                        __float2half_rn(acc[mi][nj][2 * h + 0] + bv.x);
                    st[(size_t)(cloc + 1) * 132 + r] =
                        __float2half_rn(acc[mi][nj][2 * h + 1] + bv.y);
                }
            }
        }
        __syncthreads();
        // coalesced out: thread t -> col = t>>1, rows [(t&1)*64, +64)
        __half* Vt = Qe;                      // Vt passed via Qe param
        const int col   = tid >> 1;
        const int rbase = (tid & 1) * 64;
        const int b     = tileM >> 12;        // tile fully inside one batch
        const int s0    = tileM & (SEQ - 1);
        __half* gdst = Vt + (size_t)b * DIM * SEQ
                          + (size_t)(tileN + col) * SEQ + s0 + rbase;
        const __half* ssrc = st + (size_t)col * 132 + rbase;
#pragma unroll
        for (int i = 0; i < 16; i++)          // 64 halfs = 16 x 8B
            *(uint2*)(gdst + i * 4) = *(const uint2*)(ssrc + i * 4);
    }
}

// ---------------------------------------------------------------------------
// prep: fp16 split2 operands.
// A' = [xh | xh | xl]; Bqk rows (Wq then Wk): [Wh | Wl | Wh]; Bv = Wv fp16.
// ---------------------------------------------------------------------------
__global__ void __launch_bounds__(256)
convert_x(const float* __restrict__ x, __half* __restrict__ Ax)
{
    const int idx = blockIdx.x * blockDim.x + threadIdx.x;   // < MTOT*DIM
    const int m = idx >> 10;
    const int d = idx & (DIM - 1);
    float v = x[idx];
    __half h = __float2half_rn(v);
    __half l = __float2half_rn(v - __half2float(h));
    size_t base = (size_t)m * KQK;
    Ax[base + d]            = h;
    Ax[base + DIM + d]      = h;
    Ax[base + 2 * DIM + d]  = l;
}

__global__ void __launch_bounds__(256)
convert_w(const float* __restrict__ Wq, const float* __restrict__ Wk,
          const float* __restrict__ Wv,
          __half* __restrict__ Bqk, __half* __restrict__ Bv)
{
    const int idx = blockIdx.x * blockDim.x + threadIdx.x;   // < DIM*DIM
    const int n = idx >> 10;
    const int k = idx & (DIM - 1);
    {
        float v = Wq[idx];
        __half h = __float2half_rn(v);
        __half l = __float2half_rn(v - __half2float(h));
        size_t base = (size_t)n * KQK;
        Bqk[base + k]           = h;
        Bqk[base + DIM + k]     = l;
        Bqk[base + 2 * DIM + k] = h;
    }
    {
        float v = Wk[idx];
        __half h = __float2half_rn(v);
        __half l = __float2half_rn(v - __half2float(h));
        size_t base = (size_t)(DIM + n) * KQK;
        Bqk[base + k]           = h;
        Bqk[base + DIM + k]     = l;
        Bqk[base + 2 * DIM + k] = h;
    }
    Bv[idx] = __float2half_rn(Wv[idx]);
}

__global__ void __launch_bounds__(256)
concat_bias(const float* __restrict__ bq, const float* __restrict__ bk,
            float* __restrict__ b2)
{
    const int i = blockIdx.x * blockDim.x + threadIdx.x;     // < DE
    b2[i] = (i < DIM) ? bq[i] : bk[i - DIM];
}

// ---------------------------------------------------------------------------
// softmax rows (len SEQ); fp32 pre-scaled logits in, fp16 weights out.
// ---------------------------------------------------------------------------
__global__ void __launch_bounds__(256)
softmax_rows(const float* __restrict__ S, __half* __restrict__ P)
{
    __shared__ float sm[8];
    const float4* p4 = (const float4*)(S + (size_t)blockIdx.x * SEQ);
    __half* po = P + (size_t)blockIdx.x * SEQ;
    const int t    = threadIdx.x;
    const int lane = t & 31;
    const int wid  = t >> 5;

    float v[16];
    float mx = -1e30f;
#pragma unroll
    for (int i = 0; i < 4; i++) {
        float4 x = p4[t + i * 256];
        v[4*i+0] = x.x; v[4*i+1] = x.y; v[4*i+2] = x.z; v[4*i+3] = x.w;
        mx = fmaxf(mx, fmaxf(fmaxf(x.x, x.y), fmaxf(x.z, x.w)));
    }
#pragma unroll
    for (int off = 16; off >= 1; off >>= 1)
        mx = fmaxf(mx, __shfl_xor_sync(0xffffffffu, mx, off));
    if (lane == 0) sm[wid] = mx;
    __syncthreads();
    mx = sm[0];
#pragma unroll
    for (int w = 1; w < 8; w++) mx = fmaxf(mx, sm[w]);
    __syncthreads();

    float sum = 0.0f;
#pragma unroll
    for (int i = 0; i < 16; i++) { v[i] = expf(v[i] - mx); sum += v[i]; }
#pragma unroll
    for (int off = 16; off >= 1; off >>= 1)
        sum += __shfl_xor_sync(0xffffffffu, sum, off);
    if (lane == 0) sm[wid] = sum;
    __syncthreads();
    sum = sm[0];
#pragma unroll
    for (int w = 1; w < 8; w++) sum += sm[w];
    float inv = 1.0f / sum;

    __half2* po2 = (__half2*)po;
#pragma unroll
    for (int i = 0; i < 4; i++) {
        const int e = 4 * (t + i * 256);
        po2[e / 2]     = __floats2half2_rn(v[4*i+0] * inv, v[4*i+1] * inv);
        po2[e / 2 + 1] = __floats2half2_rn(v[4*i+2] * inv, v[4*i+3] * inv);
    }
}

// ---------------------------------------------------------------------------
extern "C" void kernel_launch(void* const* d_in, const int* in_sizes, int n_in,
                              void* d_out, int out_size)
{
    const float* x  = (const float*)d_in[0];
    const float* Wq = (const float*)d_in[1];
    const float* bq = (const float*)d_in[2];
    const float* Wk = (const float*)d_in[3];
    const float* bk = (const float*)d_in[4];
    const float* Wv = (const float*)d_in[5];
    const float* bv = (const float*)d_in[6];
    const float* pb = (const float*)d_in[7];
    float* out = (float*)d_out;

    __half *Ax, *Bqk, *Bv, *Qe, *Ke, *Vt, *P;
    float *b2, *Sm;
    cudaGetSymbolAddress((void**)&Ax,  g_Ax);
    cudaGetSymbolAddress((void**)&Bqk, g_Bqk);
    cudaGetSymbolAddress((void**)&Bv,  g_Bv);
    cudaGetSymbolAddress((void**)&b2,  g_bqk);
    cudaGetSymbolAddress((void**)&Qe,  g_Qe);
    cudaGetSymbolAddress((void**)&Ke,  g_Ke);
    cudaGetSymbolAddress((void**)&Vt,  g_Vt);
    cudaGetSymbolAddress((void**)&Sm,  g_S);
    cudaGetSymbolAddress((void**)&P,   g_P);

    cudaFuncSetAttribute(hgemm_nt<EPI_STORE>,
                         cudaFuncAttributeMaxDynamicSharedMemorySize,
                         H_SMEM_BYTES);
    cudaFuncSetAttribute(hgemm_nt<EPI_THETA>,
                         cudaFuncAttributeMaxDynamicSharedMemorySize,
                         H_SMEM_BYTES);
    cudaFuncSetAttribute(hgemm_nt<EPI_VT>,
                         cudaFuncAttributeMaxDynamicSharedMemorySize,
                         H_SMEM_BYTES);
    cudaFuncSetAttribute(hgemm_nt<EPI_SIM>,
                         cudaFuncAttributeMaxDynamicSharedMemorySize,
                         H_SMEM_BYTES);

    // 0) build fp16 operands
    convert_x<<<(MTOT * DIM) / 256, 256>>>(x, Ax);
    convert_w<<<(DIM * DIM) / 256, 256>>>(Wq, Wk, Wv, Bqk, Bv);
    concat_bias<<<DE / 256, 256>>>(bq, bk, b2);

    // 1) QK projection (split2, K=3072) with fused theta epilogue -> Qe, Ke
    dim3 gQK(DE / 128, MTOT / 128, 1);
    hgemm_nt<EPI_THETA><<<gQK, 256, H_SMEM_BYTES>>>(
        Ax, Bqk, b2, nullptr, Qe, Ke, pb,
        DE, KQK, KQK, KQK, 0, 0, 0);

    // 2) V projection (plain fp16, K=1024) with fused coalesced transpose
    dim3 gV(DIM / 128, MTOT / 128, 1);
    hgemm_nt<EPI_VT><<<gV, 256, H_SMEM_BYTES>>>(
        Ax, Bv, bv, nullptr, Vt, nullptr, nullptr,
        DIM, DIM, KQK, DIM, 0, 0, 0);

    // 3) sim = Qe @ Ke^T per batch -> fp32 logits * (1/32)
    dim3 gSim(SEQ / 128, SEQ / 128, BATCH);
    hgemm_nt<EPI_SIM><<<gSim, 256, H_SMEM_BYTES>>>(
        Qe, Ke, nullptr, Sm, nullptr, nullptr, nullptr,
        SEQ, DE, DE, DE,
        (size_t)SEQ * DE, (size_t)SEQ * DE, (size_t)SEQ * SEQ);

    // 4) softmax rows (fp32 in, fp16 out)
    softmax_rows<<<BATCH * SEQ, 256>>>(Sm, P);

    // 5) out = P @ Vt^T per batch (fp16 mma k16)
    dim3 gPV(DIM / 128, SEQ / 128, BATCH);
    hgemm_nt<EPI_STORE><<<gPV, 256, H_SMEM_BYTES>>>(
        P, Vt, nullptr, out, nullptr, nullptr, nullptr,
        DIM, SEQ, SEQ, SEQ,
        (size_t)SEQ * SEQ, (size_t)DIM * SEQ, (size_t)SEQ * DIM);
}